// round 3
// baseline (speedup 1.0000x reference)
#include <cuda_runtime.h>
#include <math.h>

#define DD   512
#define NPOS 128
#define NB   32
#define LUT  512   // threads in LU kernel

// ---------------- device scratch ----------------
__device__ float g_G[DD * DD];                 // G = I - P P^T
__device__ float g_A[NPOS][DD * DD];           // per-step working matrices
__device__ float g_piv[NPOS][DD];              // pivots u_jj per step
__device__ int   g_posrank[DD];
__device__ float g_picked[NPOS];

// ---------------- kernel 0 ----------------
__global__ void posrank_kernel(const int* __restrict__ pos) {
    int t = threadIdx.x;
    if (t < DD) g_posrank[t] = 0x7fffffff;
    __syncthreads();
    if (t < NPOS) g_posrank[pos[t]] = t;
}

// ---------------- kernel 1: G = I - P P^T ----------------
__global__ void gmat_kernel(const float* __restrict__ P) {
    __shared__ float sA[16][NPOS + 1];
    __shared__ float sB[16][NPOS + 1];
    int tx = threadIdx.x, ty = threadIdx.y;
    int tid = ty * 16 + tx;
    int i0 = blockIdx.y * 16, j0 = blockIdx.x * 16;

    for (int t = tid; t < 16 * NPOS; t += 256) {
        int r = t >> 7, c = t & (NPOS - 1);
        sA[r][c] = P[(i0 + r) * NPOS + c];
        sB[r][c] = P[(j0 + r) * NPOS + c];
    }
    __syncthreads();

    float acc = 0.0f;
#pragma unroll 8
    for (int c = 0; c < NPOS; c++) acc += sA[ty][c] * sB[tx][c];

    int i = i0 + ty, j = j0 + tx;
    g_G[i * DD + j] = ((i == j) ? 1.0f : 0.0f) - acc;
}

// ---------------- kernel 2: A_k = G - diag(occ_prefix_k) ----------------
__global__ void init_kernel() {
    int k = blockIdx.y;
    int n = DD - NPOS + k + 1;
    int r0 = blockIdx.x * 32;
    for (int r = r0; r < r0 + 32 && r < n; r++) {
        int dec = (g_posrank[r] < k) ? 1 : 0;
        float* dst = g_A[k] + (size_t)r * DD;
        const float* src = g_G + (size_t)r * DD;
        for (int j = threadIdx.x; j < n; j += blockDim.x) {
            float v = src[j];
            if (j == r && dec) v -= 1.0f;
            dst[j] = v;
        }
    }
}

// ---------------- kernel 3: symmetric blocked elimination, one CTA per k ----------------
// A_k is symmetric (LDL^T). Only the lower triangle + 31-wide diagonal band are
// maintained. Panel L strip in smem (sl), pre-scaled copy sls = L*d for the
// trailing update: C[i,j] -= sum_c (L[i,c]*d_c) * L[j,c], lower tiles only.
__global__ void __launch_bounds__(LUT) lu_kernel() {
    extern __shared__ float smem[];
    float* sl   = smem;                 // [512][33] L panel
    float* sls  = smem + 512 * 33;      // [512][33] L*d panel
    float* smd  = sls + 512 * 33;       // [32][33] updated diag-block rows (U rows)
    float* sinv = smd + 32 * 33;        // [32] 1/d

    int k = blockIdx.x;
    int n = DD - NPOS + k + 1;
    float* A = g_A[k];
    const int tid = threadIdx.x;

    for (int p = 0; p < n; p += NB) {
        int rows = n - p;
        int pw = min(NB, rows);

        // ---- load column strip (coalesced, 128B per row) ----
        for (int t = tid; t < rows * NB; t += LUT) {
            int r = t >> 5, c = t & 31;
            sl[r * 33 + c] = (c < pw) ? A[(size_t)(p + r) * DD + (p + c)] : 0.0f;
        }
        __syncthreads();

        // ---- phase 1: warp 0 factors the 32x32 diag block (warp-sync, no bars) ----
        if (tid < 32) {
            int r = tid;
            float a[NB];
#pragma unroll
            for (int c = 0; c < NB; c++)
                a[c] = (r < rows) ? sl[r * 33 + c] : ((r == c) ? 1.0f : 0.0f);
#pragma unroll
            for (int c = 0; c < NB; c++) {
                float d = __shfl_sync(0xffffffffu, a[c], c);
                float inv = 1.0f / d;
                if (r == c) {
#pragma unroll
                    for (int j = 0; j < NB; j++) smd[c * 33 + j] = a[j];
                    sinv[c] = inv;
                }
                float l = a[c] * inv;
#pragma unroll
                for (int j = c + 1; j < NB; j++) {
                    float uc = __shfl_sync(0xffffffffu, a[j], c);
                    if (r > c) a[j] -= l * uc;
                }
            }
            if (r < pw) g_piv[k][p + r] = a[r];
        }
        __syncthreads();

        // ---- phase 2: row-parallel L strip (one row per thread, no column syncs) ----
        {
            int i = NB + tid;
            if (i < rows) {
                float l[NB];
#pragma unroll
                for (int c = 0; c < NB; c++) {
                    float m = sl[i * 33 + c];
#pragma unroll
                    for (int t2 = 0; t2 < NB; t2++)
                        if (t2 < c) m -= l[t2] * smd[t2 * 33 + c];
                    float lv = m * sinv[c];
                    l[c] = lv;
                    sl[i * 33 + c]  = lv;
                    sls[i * 33 + c] = m;   // m = lv * d_c (pre-scaled operand)
                }
            }
        }
        __syncthreads();

        // ---- trailing symmetric rank-32 update: lower tiles only ----
        int tr0 = p + NB;
        int tsz = rows - NB;
        if (tsz > 0) {
            int g  = tid >> 8;           // two 256-thread groups
            int lt = tid & 255;
            int tx = lt & 15, ty = lt >> 4;
            int nt = (tsz + 127) >> 7;
            int npairs = (nt * (nt + 1)) >> 1;
            for (int idx = g; idx < npairs; idx += 2) {
                int bi = 0;
                while ((((bi + 1) * (bi + 2)) >> 1) <= idx) bi++;
                int bj = idx - ((bi * (bi + 1)) >> 1);
                int i0 = bi << 7, j0 = bj << 7;

                int ii[8], jj[8]; bool ivd[8], jvd[8];
#pragma unroll
                for (int u = 0; u < 8; u++) { int il = i0 + ty + 16 * u; ivd[u] = (il < tsz); ii[u] = ivd[u] ? il : 0; }
#pragma unroll
                for (int v = 0; v < 8; v++) { int jl = j0 + tx + 16 * v; jvd[v] = (jl < tsz); jj[v] = jvd[v] ? jl : 0; }

                float acc[8][8];
#pragma unroll
                for (int u = 0; u < 8; u++)
#pragma unroll
                    for (int v = 0; v < 8; v++)
                        acc[u][v] = A[(size_t)(tr0 + ii[u]) * DD + tr0 + jj[v]];

#pragma unroll 8
                for (int c = 0; c < NB; c++) {
                    float Ls[8], Mr[8];
#pragma unroll
                    for (int u = 0; u < 8; u++) Ls[u] = sls[(NB + ii[u]) * 33 + c];
#pragma unroll
                    for (int v = 0; v < 8; v++) Mr[v] = sl[(NB + jj[v]) * 33 + c];
#pragma unroll
                    for (int u = 0; u < 8; u++)
#pragma unroll
                        for (int v = 0; v < 8; v++)
                            acc[u][v] -= Ls[u] * Mr[v];
                }
#pragma unroll
                for (int u = 0; u < 8; u++) if (ivd[u])
#pragma unroll
                    for (int v = 0; v < 8; v++) if (jvd[v])
                        A[(size_t)(tr0 + ii[u]) * DD + tr0 + jj[v]] = acc[u][v];
            }

            // corner fix: the 31-wide diagonal band crossing 128-tile boundaries
            // lies in skipped (bi, bi+1) tiles — update those elements explicitly.
            for (int bt = 1; bt < nt; bt++) {
                int base = bt << 7;
                for (int t = tid; t < 32 * 32; t += LUT) {
                    int x = t >> 5, y = t & 31;
                    int rl = base - 32 + x, cl = base + y;
                    if (y < x && cl < tsz) {
                        float a = A[(size_t)(tr0 + rl) * DD + tr0 + cl];
#pragma unroll
                        for (int c = 0; c < NB; c++)
                            a -= sls[(NB + rl) * 33 + c] * sl[(NB + cl) * 33 + c];
                        A[(size_t)(tr0 + rl) * DD + tr0 + cl] = a;
                    }
                }
            }
        }
        __syncthreads();
    }
}

// ---------------- kernel 4: probs rows via smem-staged sequential cumprod ----------------
__global__ void probs_kernel(const int* __restrict__ pos, float* __restrict__ out) {
    int k = blockIdx.x;
    __shared__ float sp[DD];
    __shared__ float srow[DD];
    float* row = out + (size_t)k * DD;
    for (int i = threadIdx.x; i < DD; i += blockDim.x) {
        sp[i] = g_piv[k][i];
        srow[i] = 0.0f;
    }
    __syncthreads();
    if (threadIdx.x == 0) {
        int xmin = (k == 0) ? 0 : (pos[k - 1] + 1);
        int xmax = DD - NPOS + k + 1;
        int pk = pos[k];
        float c = 1.0f, picked = 0.0f;
        for (int i = xmin; i < xmax; i++) {
            float u = sp[i];
            float pr = c * (1.0f - u);
            pr = (fabsf(pr) > 1e-15f) ? pr : 0.0f;
            srow[i] = pr;
            if (i == pk) picked = pr;
            c *= u;
        }
        g_picked[k] = logf(picked);
    }
    __syncthreads();
    for (int i = threadIdx.x; i < DD; i += blockDim.x) row[i] = srow[i];
}

// ---------------- kernel 5: deterministic log-sum ----------------
__global__ void finalize_kernel(float* __restrict__ out, int out_size) {
    __shared__ float s[NPOS];
    if (threadIdx.x < NPOS) s[threadIdx.x] = g_picked[threadIdx.x];
    __syncthreads();
    if (threadIdx.x == 0) {
        float t = 0.0f;
        for (int i = 0; i < NPOS; i++) t += s[i];
        out[out_size - 1] = t;
    }
}

// ---------------- launch ----------------
extern "C" void kernel_launch(void* const* d_in, const int* in_sizes, int n_in,
                              void* d_out, int out_size) {
    const float* P   = (const float*)d_in[0];
    const int*   pos = (const int*)d_in[1];
    float*       out = (float*)d_out;

    size_t lu_smem = (size_t)(2 * 512 * 33 + 32 * 33 + 32) * sizeof(float); // ~139.9 KB
    cudaFuncSetAttribute(lu_kernel, cudaFuncAttributeMaxDynamicSharedMemorySize, (int)lu_smem);

    posrank_kernel<<<1, 512>>>(pos);
    gmat_kernel<<<dim3(DD / 16, DD / 16), dim3(16, 16)>>>(P);
    init_kernel<<<dim3(16, NPOS), 256>>>();
    lu_kernel<<<NPOS, LUT, lu_smem>>>();
    probs_kernel<<<NPOS, 256>>>(pos, out);
    finalize_kernel<<<1, 128>>>(out, out_size);
}

// round 6
// speedup vs baseline: 1.0139x; 1.0139x over previous
#include <cuda_runtime.h>
#include <math.h>

#define DD   512
#define NPOS 128
#define NB   32
#define LUT  512   // threads in LU kernel

// ---------------- device scratch ----------------
__device__ float g_G[DD * DD];                 // G = I - P P^T
__device__ float g_A[NPOS][DD * DD];           // per-step working matrices
__device__ float g_piv[NPOS][DD];              // pivots u_jj per step
__device__ int   g_posrank[DD];
__device__ float g_picked[NPOS];

// ---------------- kernel 0 ----------------
__global__ void posrank_kernel(const int* __restrict__ pos) {
    int t = threadIdx.x;
    if (t < DD) g_posrank[t] = 0x7fffffff;
    __syncthreads();
    if (t < NPOS) g_posrank[pos[t]] = t;
}

// ---------------- kernel 1: G = I - P P^T ----------------
__global__ void gmat_kernel(const float* __restrict__ P) {
    __shared__ float sA[16][NPOS + 1];
    __shared__ float sB[16][NPOS + 1];
    int tx = threadIdx.x, ty = threadIdx.y;
    int tid = ty * 16 + tx;
    int i0 = blockIdx.y * 16, j0 = blockIdx.x * 16;

    for (int t = tid; t < 16 * NPOS; t += 256) {
        int r = t >> 7, c = t & (NPOS - 1);
        sA[r][c] = P[(i0 + r) * NPOS + c];
        sB[r][c] = P[(j0 + r) * NPOS + c];
    }
    __syncthreads();

    float acc = 0.0f;
#pragma unroll 8
    for (int c = 0; c < NPOS; c++) acc += sA[ty][c] * sB[tx][c];

    int i = i0 + ty, j = j0 + tx;
    g_G[i * DD + j] = ((i == j) ? 1.0f : 0.0f) - acc;
}

// ---------------- kernel 2: A_k = G - diag(occ_prefix_k) ----------------
__global__ void init_kernel() {
    int k = blockIdx.y;
    int n = DD - NPOS + k + 1;
    int r0 = blockIdx.x * 32;
    for (int r = r0; r < r0 + 32 && r < n; r++) {
        int dec = (g_posrank[r] < k) ? 1 : 0;
        float* dst = g_A[k] + (size_t)r * DD;
        const float* src = g_G + (size_t)r * DD;
        for (int j = threadIdx.x; j < n; j += blockDim.x) {
            float v = src[j];
            if (j == r && dec) v -= 1.0f;
            dst[j] = v;
        }
    }
}

// ---------------- kernel 3: symmetric blocked elimination, one CTA per k ----------------
// LDL^T structure: maintain lower triangle + 31-wide upper band.
// Trailing: C[i,j] -= sum_c (L[i,c]*d_c) * L[j,c], lower/diag 128-tiles + band corner fix.
// 512 threads, 8x4 register tiles (acc=32 regs -> no spills at the 128-reg cap).
__global__ void __launch_bounds__(LUT) lu_kernel() {
    extern __shared__ float smem[];
    float* sl   = smem;                 // [512][33] L panel
    float* sls  = smem + 512 * 33;      // [512][33] L*d panel (= unscaled m)
    float* smd  = sls + 512 * 33;       // [32][33] diag-block U rows
    float* sinv = smd + 32 * 33;        // [32] 1/d

    int k = blockIdx.x;
    int n = DD - NPOS + k + 1;
    float* A = g_A[k];
    const int tid = threadIdx.x;
    const int tx = tid & 31;            // j-dim lane
    const int ty = tid >> 5;            // i-dim warp id (0..15)

    for (int p = 0; p < n; p += NB) {
        int rows = n - p;
        int pw = min(NB, rows);

        // ---- load column strip (coalesced, 128B per row) ----
        for (int t = tid; t < rows * NB; t += LUT) {
            int r = t >> 5, c = t & 31;
            sl[r * 33 + c] = (c < pw) ? A[(size_t)(p + r) * DD + (p + c)] : 0.0f;
        }
        __syncthreads();

        // ---- phase 1: warp 0 factors the 32x32 diag block (warp-sync) ----
        if (tid < 32) {
            int r = tid;
            float a[NB];
#pragma unroll
            for (int c = 0; c < NB; c++)
                a[c] = (r < rows) ? sl[r * 33 + c] : ((r == c) ? 1.0f : 0.0f);
#pragma unroll
            for (int c = 0; c < NB; c++) {
                float d = __shfl_sync(0xffffffffu, a[c], c);
                float inv = 1.0f / d;
                if (r == c) {
#pragma unroll
                    for (int j = 0; j < NB; j++) smd[c * 33 + j] = a[j];
                    sinv[c] = inv;
                }
                float l = a[c] * inv;
#pragma unroll
                for (int j = c + 1; j < NB; j++) {
                    float uc = __shfl_sync(0xffffffffu, a[j], c);
                    if (r > c) a[j] -= l * uc;
                }
            }
            if (r < pw) g_piv[k][p + r] = a[r];
        }
        __syncthreads();

        // ---- phase 2: row-parallel L strip (one row per thread) ----
        {
            int i = NB + tid;
            if (i < rows) {
                float l[NB];
#pragma unroll
                for (int c = 0; c < NB; c++) {
                    float m = sl[i * 33 + c];
#pragma unroll
                    for (int t2 = 0; t2 < NB; t2++)
                        if (t2 < c) m -= l[t2] * smd[t2 * 33 + c];
                    float lv = m * sinv[c];
                    l[c] = lv;
                    sl[i * 33 + c]  = lv;   // L
                    sls[i * 33 + c] = m;    // L*d
                }
            }
        }
        __syncthreads();

        // ---- trailing symmetric rank-32 update: whole CTA per 128x128 tile ----
        int tr0 = p + NB;
        int tsz = rows - NB;
        if (tsz > 0) {
            int nt = (tsz + 127) >> 7;
            int npairs = (nt * (nt + 1)) >> 1;
            for (int idx = 0; idx < npairs; idx++) {
                int bi = 0;
                while ((((bi + 1) * (bi + 2)) >> 1) <= idx) bi++;
                int bj = idx - ((bi * (bi + 1)) >> 1);
                int i0 = bi << 7, j0 = bj << 7;

                int ii[8], jj[4]; bool ivd[8], jvd[4];
#pragma unroll
                for (int u = 0; u < 8; u++) { int il = i0 + ty + 16 * u; ivd[u] = (il < tsz); ii[u] = ivd[u] ? il : 0; }
#pragma unroll
                for (int v = 0; v < 4; v++) { int jl = j0 + tx + 32 * v; jvd[v] = (jl < tsz); jj[v] = jvd[v] ? jl : 0; }

                float acc[8][4];
#pragma unroll
                for (int u = 0; u < 8; u++)
#pragma unroll
                    for (int v = 0; v < 4; v++)
                        acc[u][v] = A[(size_t)(tr0 + ii[u]) * DD + tr0 + jj[v]];

#pragma unroll 8
                for (int c = 0; c < NB; c++) {
                    float Ls[8], Mr[4];
#pragma unroll
                    for (int u = 0; u < 8; u++) Ls[u] = sls[(NB + ii[u]) * 33 + c];
#pragma unroll
                    for (int v = 0; v < 4; v++) Mr[v] = sl[(NB + jj[v]) * 33 + c];
#pragma unroll
                    for (int u = 0; u < 8; u++)
#pragma unroll
                        for (int v = 0; v < 4; v++)
                            acc[u][v] -= Ls[u] * Mr[v];
                }
#pragma unroll
                for (int u = 0; u < 8; u++) if (ivd[u])
#pragma unroll
                    for (int v = 0; v < 4; v++) if (jvd[v])
                        A[(size_t)(tr0 + ii[u]) * DD + tr0 + jj[v]] = acc[u][v];
            }

            // corner fix: 31-wide upper band crossing 128-tile boundaries
            for (int bt = 1; bt < nt; bt++) {
                int base = bt << 7;
                for (int t = tid; t < 32 * 32; t += LUT) {
                    int x = t >> 5, y = t & 31;
                    int rl = base - 32 + x, cl = base + y;
                    if (y < x && cl < tsz) {
                        float a = A[(size_t)(tr0 + rl) * DD + tr0 + cl];
#pragma unroll
                        for (int c = 0; c < NB; c++)
                            a -= sls[(NB + rl) * 33 + c] * sl[(NB + cl) * 33 + c];
                        A[(size_t)(tr0 + rl) * DD + tr0 + cl] = a;
                    }
                }
            }
        }
        __syncthreads();
    }
}

// ---------------- kernel 4: probs rows via smem-staged sequential cumprod ----------------
__global__ void probs_kernel(const int* __restrict__ pos, float* __restrict__ out) {
    int k = blockIdx.x;
    __shared__ float sp[DD];
    __shared__ float srow[DD];
    float* row = out + (size_t)k * DD;
    for (int i = threadIdx.x; i < DD; i += blockDim.x) {
        sp[i] = g_piv[k][i];
        srow[i] = 0.0f;
    }
    __syncthreads();
    if (threadIdx.x == 0) {
        int xmin = (k == 0) ? 0 : (pos[k - 1] + 1);
        int xmax = DD - NPOS + k + 1;
        int pk = pos[k];
        float c = 1.0f, picked = 0.0f;
        for (int i = xmin; i < xmax; i++) {
            float u = sp[i];
            float pr = c * (1.0f - u);
            pr = (fabsf(pr) > 1e-15f) ? pr : 0.0f;
            srow[i] = pr;
            if (i == pk) picked = pr;
            c *= u;
        }
        g_picked[k] = logf(picked);
    }
    __syncthreads();
    for (int i = threadIdx.x; i < DD; i += blockDim.x) row[i] = srow[i];
}

// ---------------- kernel 5: deterministic log-sum ----------------
__global__ void finalize_kernel(float* __restrict__ out, int out_size) {
    __shared__ float s[NPOS];
    if (threadIdx.x < NPOS) s[threadIdx.x] = g_picked[threadIdx.x];
    __syncthreads();
    if (threadIdx.x == 0) {
        float t = 0.0f;
        for (int i = 0; i < NPOS; i++) t += s[i];
        out[out_size - 1] = t;
    }
}

// ---------------- launch ----------------
extern "C" void kernel_launch(void* const* d_in, const int* in_sizes, int n_in,
                              void* d_out, int out_size) {
    const float* P   = (const float*)d_in[0];
    const int*   pos = (const int*)d_in[1];
    float*       out = (float*)d_out;

    size_t lu_smem = (size_t)(2 * 512 * 33 + 32 * 33 + 32) * sizeof(float); // ~139.9 KB
    cudaFuncSetAttribute(lu_kernel, cudaFuncAttributeMaxDynamicSharedMemorySize, (int)lu_smem);

    posrank_kernel<<<1, 512>>>(pos);
    gmat_kernel<<<dim3(DD / 16, DD / 16), dim3(16, 16)>>>(P);
    init_kernel<<<dim3(16, NPOS), 256>>>();
    lu_kernel<<<NPOS, LUT, lu_smem>>>();
    probs_kernel<<<NPOS, 256>>>(pos, out);
    finalize_kernel<<<1, 128>>>(out, out_size);
}

// round 10
// speedup vs baseline: 3.2736x; 3.2287x over previous
#include <cuda_runtime.h>
#include <math.h>

#define DD   512
#define NPOS 128
#define NB   32
#define LUT  256   // threads in LU kernel (R2 configuration)

// ---------------- device scratch ----------------
__device__ float g_G[DD * DD];                 // G = I - P P^T
__device__ float g_A[NPOS][DD * DD];           // per-step working matrices
__device__ float g_piv[NPOS][DD];              // pivots u_jj per step
__device__ int   g_posrank[DD];
__device__ float g_picked[NPOS];

// ---------------- kernel 0 ----------------
__global__ void posrank_kernel(const int* __restrict__ pos) {
    int t = threadIdx.x;
    if (t < DD) g_posrank[t] = 0x7fffffff;
    __syncthreads();
    if (t < NPOS) g_posrank[pos[t]] = t;
}

// ---------------- kernel 1: G = I - P P^T ----------------
__global__ void gmat_kernel(const float* __restrict__ P) {
    __shared__ float sA[16][NPOS + 1];
    __shared__ float sB[16][NPOS + 1];
    int tx = threadIdx.x, ty = threadIdx.y;
    int tid = ty * 16 + tx;
    int i0 = blockIdx.y * 16, j0 = blockIdx.x * 16;

    for (int t = tid; t < 16 * NPOS; t += 256) {
        int r = t >> 7, c = t & (NPOS - 1);
        sA[r][c] = P[(i0 + r) * NPOS + c];
        sB[r][c] = P[(j0 + r) * NPOS + c];
    }
    __syncthreads();

    float acc = 0.0f;
#pragma unroll 8
    for (int c = 0; c < NPOS; c++) acc += sA[ty][c] * sB[tx][c];

    int i = i0 + ty, j = j0 + tx;
    g_G[i * DD + j] = ((i == j) ? 1.0f : 0.0f) - acc;
}

// ---------------- kernel 2: A_k = G - diag(occ_prefix_k) ----------------
__global__ void init_kernel() {
    int k = blockIdx.y;
    int n = DD - NPOS + k + 1;
    int r0 = blockIdx.x * 32;
    for (int r = r0; r < r0 + 32 && r < n; r++) {
        int dec = (g_posrank[r] < k) ? 1 : 0;
        float* dst = g_A[k] + (size_t)r * DD;
        const float* src = g_G + (size_t)r * DD;
        for (int j = threadIdx.x; j < n; j += blockDim.x) {
            float v = src[j];
            if (j == r && dec) v -= 1.0f;
            dst[j] = v;
        }
    }
}

// ---------------- kernel 3: blocked elimination, one CTA per k ----------------
// R2 structure (256 threads, 8x8 register tiles, per-column panel factor) with
// ONE change: symmetric trailing update (lower tiles only + band corner fix).
// A_k symmetric: U[c,j] = d_c L[j,c] = M[j,c]  =>  C[i,j] -= L[i,c]*M[j,c].
__global__ void lu_kernel() {
    int k = blockIdx.x;
    int n = DD - NPOS + k + 1;
    float* A = g_A[k];
    extern __shared__ float smem[];
    float* sm = smem;              // [512][33] unscaled panel M (= L*d)
    float* sl = smem + DD * 33;    // [512][33] scaled L panel
    const int tid = threadIdx.x;

    for (int p = 0; p < n; p += NB) {
        int pw   = min(NB, n - p);
        int rows = n - p;

        // load panel (coalesced: 32 consecutive floats per row)
        for (int t = tid; t < rows * NB; t += LUT) {
            int r = t >> 5, c = t & 31;
            float v = (c < pw) ? A[(size_t)(p + r) * DD + (p + c)] : 0.0f;
            sm[r * 33 + c] = v;
        }
        __syncthreads();

        // factor panel columns (R2: per-column barrier)
        for (int c = 0; c < pw; c++) {
            float d = sm[c * 33 + c];
            float inv = 1.0f / d;
            for (int i = c + 1 + tid; i < rows; i += LUT) {
                float m = sm[i * 33 + c];
                float l = m * inv;
                sl[i * 33 + c] = l;
#pragma unroll
                for (int j = c + 1; j < NB; j++) {
                    if (j < pw) sm[i * 33 + j] -= l * sm[c * 33 + j];
                }
            }
            __syncthreads();
        }

        // record pivots
        if (tid < pw) g_piv[k][p + tid] = sm[tid * 33 + tid];

        // trailing symmetric rank-pw update: LOWER tiles only (jb <= ib)
        int tr0 = p + pw;
        int tsz = n - tr0;
        if (tsz > 0) {
            int tx = tid & 15, ty = tid >> 4;   // 16x16 thread grid
            for (int ib = 0; ib < tsz; ib += 128) {
                for (int jb = 0; jb <= ib; jb += 128) {
                    int iidx[8], jidx[8];
                    bool iv[8], jv[8];
#pragma unroll
                    for (int u = 0; u < 8; u++) {
                        int il = ib + ty + 16 * u;
                        iv[u] = (il < tsz); iidx[u] = iv[u] ? il : 0;
                    }
#pragma unroll
                    for (int v = 0; v < 8; v++) {
                        int jl = jb + tx + 16 * v;
                        jv[v] = (jl < tsz); jidx[v] = jv[v] ? jl : 0;
                    }
                    float acc[8][8];
#pragma unroll
                    for (int u = 0; u < 8; u++)
#pragma unroll
                        for (int v = 0; v < 8; v++)
                            acc[u][v] = (iv[u] && jv[v])
                                ? A[(size_t)(tr0 + iidx[u]) * DD + tr0 + jidx[v]] : 0.0f;

                    for (int c = 0; c < pw; c++) {
                        float Lr[8], Mr[8];
#pragma unroll
                        for (int u = 0; u < 8; u++) Lr[u] = sl[(pw + iidx[u]) * 33 + c];
#pragma unroll
                        for (int v = 0; v < 8; v++) Mr[v] = sm[(pw + jidx[v]) * 33 + c];
#pragma unroll
                        for (int u = 0; u < 8; u++)
#pragma unroll
                            for (int v = 0; v < 8; v++)
                                acc[u][v] -= Lr[u] * Mr[v];
                    }
#pragma unroll
                    for (int u = 0; u < 8; u++)
#pragma unroll
                        for (int v = 0; v < 8; v++)
                            if (iv[u] && jv[v])
                                A[(size_t)(tr0 + iidx[u]) * DD + tr0 + jidx[v]] = acc[u][v];
                }
            }

            // corner fix: 31-wide upper band crossing 128-tile boundaries lies in
            // skipped strictly-upper tiles — update those elements explicitly.
            for (int bt = 1; bt * 128 < tsz; bt++) {
                int base = bt << 7;
                for (int t = tid; t < 32 * 32; t += LUT) {
                    int x = t >> 5, y = t & 31;
                    int rl = base - 32 + x, cl = base + y;
                    if (y < x && cl < tsz) {
                        float a = A[(size_t)(tr0 + rl) * DD + tr0 + cl];
#pragma unroll
                        for (int c = 0; c < NB; c++)
                            a -= sl[(pw + rl) * 33 + c] * sm[(pw + cl) * 33 + c];
                        A[(size_t)(tr0 + rl) * DD + tr0 + cl] = a;
                    }
                }
            }
        }
        __syncthreads();
    }
}

// ---------------- kernel 4: probs rows via smem-staged sequential cumprod ----------------
__global__ void probs_kernel(const int* __restrict__ pos, float* __restrict__ out) {
    int k = blockIdx.x;
    __shared__ float sp[DD];
    __shared__ float srow[DD];
    float* row = out + (size_t)k * DD;
    for (int i = threadIdx.x; i < DD; i += blockDim.x) {
        sp[i] = g_piv[k][i];
        srow[i] = 0.0f;
    }
    __syncthreads();
    if (threadIdx.x == 0) {
        int xmin = (k == 0) ? 0 : (pos[k - 1] + 1);
        int xmax = DD - NPOS + k + 1;
        int pk = pos[k];
        float c = 1.0f, picked = 0.0f;
        for (int i = xmin; i < xmax; i++) {
            float u = sp[i];
            float pr = c * (1.0f - u);
            pr = (fabsf(pr) > 1e-15f) ? pr : 0.0f;
            srow[i] = pr;
            if (i == pk) picked = pr;
            c *= u;
        }
        g_picked[k] = logf(picked);
    }
    __syncthreads();
    for (int i = threadIdx.x; i < DD; i += blockDim.x) row[i] = srow[i];
}

// ---------------- kernel 5: deterministic log-sum ----------------
__global__ void finalize_kernel(float* __restrict__ out, int out_size) {
    __shared__ float s[NPOS];
    if (threadIdx.x < NPOS) s[threadIdx.x] = g_picked[threadIdx.x];
    __syncthreads();
    if (threadIdx.x == 0) {
        float t = 0.0f;
        for (int i = 0; i < NPOS; i++) t += s[i];
        out[out_size - 1] = t;
    }
}

// ---------------- launch ----------------
extern "C" void kernel_launch(void* const* d_in, const int* in_sizes, int n_in,
                              void* d_out, int out_size) {
    const float* P   = (const float*)d_in[0];
    const int*   pos = (const int*)d_in[1];
    float*       out = (float*)d_out;

    size_t lu_smem = (size_t)2 * DD * 33 * sizeof(float);   // 135168 B (R2 layout)
    cudaFuncSetAttribute(lu_kernel, cudaFuncAttributeMaxDynamicSharedMemorySize, (int)lu_smem);

    posrank_kernel<<<1, 512>>>(pos);
    gmat_kernel<<<dim3(DD / 16, DD / 16), dim3(16, 16)>>>(P);
    init_kernel<<<dim3(16, NPOS), 256>>>();
    lu_kernel<<<NPOS, LUT, lu_smem>>>();
    probs_kernel<<<NPOS, 256>>>(pos, out);
    finalize_kernel<<<1, 128>>>(out, out_size);
}

// round 13
// speedup vs baseline: 4.3500x; 1.3288x over previous
#include <cuda_runtime.h>
#include <math.h>

#define DD   512
#define NPOS 128
#define NB   32
#define LUT  256   // threads in LU kernel (R2/R10 configuration)

// ---------------- device scratch ----------------
__device__ float g_G[DD * DD];                 // G = I - P P^T
__device__ float g_A[NPOS][DD * DD];           // per-step working matrices
__device__ float g_piv[NPOS][DD];              // pivots u_jj per step
__device__ int   g_posrank[DD];
__device__ float g_picked[NPOS];

// ---------------- kernel 0 ----------------
__global__ void posrank_kernel(const int* __restrict__ pos) {
    int t = threadIdx.x;
    if (t < DD) g_posrank[t] = 0x7fffffff;
    __syncthreads();
    if (t < NPOS) g_posrank[pos[t]] = t;
}

// ---------------- kernel 1: G = I - P P^T ----------------
__global__ void gmat_kernel(const float* __restrict__ P) {
    __shared__ float sA[16][NPOS + 1];
    __shared__ float sB[16][NPOS + 1];
    int tx = threadIdx.x, ty = threadIdx.y;
    int tid = ty * 16 + tx;
    int i0 = blockIdx.y * 16, j0 = blockIdx.x * 16;

    for (int t = tid; t < 16 * NPOS; t += 256) {
        int r = t >> 7, c = t & (NPOS - 1);
        sA[r][c] = P[(i0 + r) * NPOS + c];
        sB[r][c] = P[(j0 + r) * NPOS + c];
    }
    __syncthreads();

    float acc = 0.0f;
#pragma unroll 8
    for (int c = 0; c < NPOS; c++) acc += sA[ty][c] * sB[tx][c];

    int i = i0 + ty, j = j0 + tx;
    g_G[i * DD + j] = ((i == j) ? 1.0f : 0.0f) - acc;
}

// ---------------- kernel 2: A_k = G - diag(occ_prefix_k) ----------------
__global__ void init_kernel() {
    int k = blockIdx.y;
    int n = DD - NPOS + k + 1;
    int r0 = blockIdx.x * 32;
    for (int r = r0; r < r0 + 32 && r < n; r++) {
        int dec = (g_posrank[r] < k) ? 1 : 0;
        float* dst = g_A[k] + (size_t)r * DD;
        const float* src = g_G + (size_t)r * DD;
        for (int j = threadIdx.x; j < n; j += blockDim.x) {
            float v = src[j];
            if (j == r && dec) v -= 1.0f;
            dst[j] = v;
        }
    }
}

// ---------------- kernel 3: blocked elimination, one CTA per k ----------------
// R10 structure (256 threads, 8x8 tiles, symmetric lower-only trailing + corner
// fix) with ONE change: the panel factorization is now two-phase —
//   phase 1: warp 0 factors the 32x32 diag block warp-synchronously (shfl),
//   phase 2: row-parallel L strip, registers, 2 barriers/panel instead of 32.
__global__ void lu_kernel() {
    int k = blockIdx.x;
    int n = DD - NPOS + k + 1;
    float* A = g_A[k];
    extern __shared__ float smem[];
    float* sm   = smem;                     // [512][33] unscaled panel M (= L*d)
    float* sl   = smem + DD * 33;           // [512][33] scaled L panel
    float* smd  = sl + DD * 33;             // [32][33] diag-block U rows
    float* sinv = smd + 32 * 33;            // [32] 1/d
    const int tid = threadIdx.x;

    for (int p = 0; p < n; p += NB) {
        int pw   = min(NB, n - p);
        int rows = n - p;

        // load panel (coalesced: 32 consecutive floats per row)
        for (int t = tid; t < rows * NB; t += LUT) {
            int r = t >> 5, c = t & 31;
            float v = (c < pw) ? A[(size_t)(p + r) * DD + (p + c)] : 0.0f;
            sm[r * 33 + c] = v;
        }
        __syncthreads();

        // ---- phase 1: warp 0 factors the 32x32 diag block (warp-sync, shfl) ----
        if (tid < 32) {
            int r = tid;
            float a[NB];
#pragma unroll
            for (int c = 0; c < NB; c++)
                a[c] = (r < rows) ? sm[r * 33 + c] : ((r == c) ? 1.0f : 0.0f);
#pragma unroll
            for (int c = 0; c < NB; c++) {
                float d = __shfl_sync(0xffffffffu, a[c], c);
                float inv = 1.0f / d;
                if (r == c) {
#pragma unroll
                    for (int j = 0; j < NB; j++) smd[c * 33 + j] = a[j];
                    sinv[c] = inv;
                }
                float l = a[c] * inv;
#pragma unroll
                for (int j = c + 1; j < NB; j++) {
                    float uc = __shfl_sync(0xffffffffu, a[j], c);
                    if (r > c) a[j] -= l * uc;
                }
            }
            if (r < pw) g_piv[k][p + r] = a[r];
        }
        __syncthreads();

        // ---- phase 2: row-parallel L strip (<=2 independent rows per thread) ----
        for (int i = NB + tid; i < rows; i += LUT) {
            float l[NB];
#pragma unroll
            for (int c = 0; c < NB; c++) {
                float m = sm[i * 33 + c];
#pragma unroll
                for (int t2 = 0; t2 < NB; t2++)
                    if (t2 < c) m -= l[t2] * smd[t2 * 33 + c];
                float lv = m * sinv[c];
                l[c] = lv;
                sl[i * 33 + c] = lv;   // L
                sm[i * 33 + c] = m;    // M = L*d
            }
        }
        __syncthreads();

        // trailing symmetric rank-pw update: LOWER tiles only (jb <= ib)
        int tr0 = p + pw;
        int tsz = n - tr0;
        if (tsz > 0) {
            int tx = tid & 15, ty = tid >> 4;   // 16x16 thread grid
            for (int ib = 0; ib < tsz; ib += 128) {
                for (int jb = 0; jb <= ib; jb += 128) {
                    int iidx[8], jidx[8];
                    bool iv[8], jv[8];
#pragma unroll
                    for (int u = 0; u < 8; u++) {
                        int il = ib + ty + 16 * u;
                        iv[u] = (il < tsz); iidx[u] = iv[u] ? il : 0;
                    }
#pragma unroll
                    for (int v = 0; v < 8; v++) {
                        int jl = jb + tx + 16 * v;
                        jv[v] = (jl < tsz); jidx[v] = jv[v] ? jl : 0;
                    }
                    float acc[8][8];
#pragma unroll
                    for (int u = 0; u < 8; u++)
#pragma unroll
                        for (int v = 0; v < 8; v++)
                            acc[u][v] = (iv[u] && jv[v])
                                ? A[(size_t)(tr0 + iidx[u]) * DD + tr0 + jidx[v]] : 0.0f;

                    for (int c = 0; c < pw; c++) {
                        float Lr[8], Mr[8];
#pragma unroll
                        for (int u = 0; u < 8; u++) Lr[u] = sl[(pw + iidx[u]) * 33 + c];
#pragma unroll
                        for (int v = 0; v < 8; v++) Mr[v] = sm[(pw + jidx[v]) * 33 + c];
#pragma unroll
                        for (int u = 0; u < 8; u++)
#pragma unroll
                            for (int v = 0; v < 8; v++)
                                acc[u][v] -= Lr[u] * Mr[v];
                    }
#pragma unroll
                    for (int u = 0; u < 8; u++)
#pragma unroll
                        for (int v = 0; v < 8; v++)
                            if (iv[u] && jv[v])
                                A[(size_t)(tr0 + iidx[u]) * DD + tr0 + jidx[v]] = acc[u][v];
                }
            }

            // corner fix: 31-wide upper band crossing 128-tile boundaries lies in
            // skipped strictly-upper tiles — update those elements explicitly.
            for (int bt = 1; bt * 128 < tsz; bt++) {
                int base = bt << 7;
                for (int t = tid; t < 32 * 32; t += LUT) {
                    int x = t >> 5, y = t & 31;
                    int rl = base - 32 + x, cl = base + y;
                    if (y < x && cl < tsz) {
                        float a = A[(size_t)(tr0 + rl) * DD + tr0 + cl];
#pragma unroll
                        for (int c = 0; c < NB; c++)
                            a -= sl[(pw + rl) * 33 + c] * sm[(pw + cl) * 33 + c];
                        A[(size_t)(tr0 + rl) * DD + tr0 + cl] = a;
                    }
                }
            }
        }
        __syncthreads();
    }
}

// ---------------- kernel 4: probs rows via smem-staged sequential cumprod ----------------
__global__ void probs_kernel(const int* __restrict__ pos, float* __restrict__ out) {
    int k = blockIdx.x;
    __shared__ float sp[DD];
    __shared__ float srow[DD];
    float* row = out + (size_t)k * DD;
    for (int i = threadIdx.x; i < DD; i += blockDim.x) {
        sp[i] = g_piv[k][i];
        srow[i] = 0.0f;
    }
    __syncthreads();
    if (threadIdx.x == 0) {
        int xmin = (k == 0) ? 0 : (pos[k - 1] + 1);
        int xmax = DD - NPOS + k + 1;
        int pk = pos[k];
        float c = 1.0f, picked = 0.0f;
        for (int i = xmin; i < xmax; i++) {
            float u = sp[i];
            float pr = c * (1.0f - u);
            pr = (fabsf(pr) > 1e-15f) ? pr : 0.0f;
            srow[i] = pr;
            if (i == pk) picked = pr;
            c *= u;
        }
        g_picked[k] = logf(picked);
    }
    __syncthreads();
    for (int i = threadIdx.x; i < DD; i += blockDim.x) row[i] = srow[i];
}

// ---------------- kernel 5: deterministic log-sum ----------------
__global__ void finalize_kernel(float* __restrict__ out, int out_size) {
    __shared__ float s[NPOS];
    if (threadIdx.x < NPOS) s[threadIdx.x] = g_picked[threadIdx.x];
    __syncthreads();
    if (threadIdx.x == 0) {
        float t = 0.0f;
        for (int i = 0; i < NPOS; i++) t += s[i];
        out[out_size - 1] = t;
    }
}

// ---------------- launch ----------------
extern "C" void kernel_launch(void* const* d_in, const int* in_sizes, int n_in,
                              void* d_out, int out_size) {
    const float* P   = (const float*)d_in[0];
    const int*   pos = (const int*)d_in[1];
    float*       out = (float*)d_out;

    size_t lu_smem = (size_t)(2 * DD * 33 + 32 * 33 + 32) * sizeof(float); // ~139.5 KB
    cudaFuncSetAttribute(lu_kernel, cudaFuncAttributeMaxDynamicSharedMemorySize, (int)lu_smem);

    posrank_kernel<<<1, 512>>>(pos);
    gmat_kernel<<<dim3(DD / 16, DD / 16), dim3(16, 16)>>>(P);
    init_kernel<<<dim3(16, NPOS), 256>>>();
    lu_kernel<<<NPOS, LUT, lu_smem>>>();
    probs_kernel<<<NPOS, 256>>>(pos, out);
    finalize_kernel<<<1, 128>>>(out, out_size);
}